// round 16
// baseline (speedup 1.0000x reference)
#include <cuda_runtime.h>
#include <cuda_fp16.h>
#include <cstdint>

#define NNODES 50000
#define NEDGES 800000
#define MTILES 391
#define NPAD   (MTILES*128)   // 50048
#define HDIM   128
#define OUTC   64
#define SCAN_B 98             // ceil(50000/512)
#define ZERO_B 196            // ceil(50000/256)
#define WP_TOT (4*8192 + 4096)   // packed half2 pairs: 4x(64*128) + 64*64
#define WSPL_B 144            // WP_TOT/256
#define XPK_B  3125           // x-pack blocks (1.6M float4 / (256*2))

// ------------- scratch: __device__ globals, touched ONLY from device code --
__device__ __align__(16) float    g_z[(size_t)NPAD*HDIM];
__device__ __align__(16) float    g_t[(size_t)NPAD*HDIM];
__device__ __align__(16) float    g_h[(size_t)NPAD*HDIM];
__device__ __align__(16) uint32_t g_xh[(size_t)NPAD*64];   // x as packed half2
__device__ __align__(16) uint32_t g_hh[(size_t)NPAD*64];   // h1 as packed half2
__device__ __align__(16) uint32_t g_wh2[WP_TOT];
__device__ __align__(16) uint32_t g_wl2[WP_TOT];
__device__ int g_cnt[NNODES];
__device__ int g_fill[NNODES];
__device__ int g_rowptr[NNODES+1];
__device__ int g_srcs[NEDGES];
__device__ int g_bsums[SCAN_B];
__device__ int g_is64;

// 0=g_z 1=g_t 2=g_h  (fp32 buffers)
template<int ID> __device__ __forceinline__ float* buf(){
    if constexpr (ID == 0) return g_z;
    else if constexpr (ID == 1) return g_t;
    else return g_h;
}

__device__ __forceinline__ int clampN(int i){
    i = max(i, 0);
    return min(i, NNODES - 1);
}

__device__ __forceinline__ uint32_t packh2(float a, float b){
    __half2 h = __floats2half2_rn(a, b);
    return *reinterpret_cast<uint32_t*>(&h);
}
__device__ __forceinline__ uint32_t packsplit_lo(float a, float b){
    __half ha = __float2half_rn(a), hb = __float2half_rn(b);
    __half2 l = __halves2half2(__float2half_rn(a - __half2float(ha)),
                               __float2half_rn(b - __half2float(hb)));
    return *reinterpret_cast<uint32_t*>(&l);
}
__device__ __forceinline__ float2 h2f2(uint32_t u){
    return __half22float2(*reinterpret_cast<__half2*>(&u));
}

__device__ __forceinline__ void mma16(float* c, uint32_t a0, uint32_t a1,
                                      uint32_t a2, uint32_t a3,
                                      uint32_t b0, uint32_t b1){
    asm("mma.sync.aligned.m16n8k16.row.col.f32.f16.f16.f32 "
        "{%0,%1,%2,%3},{%4,%5,%6,%7},{%8,%9},{%0,%1,%2,%3};"
        : "+f"(c[0]), "+f"(c[1]), "+f"(c[2]), "+f"(c[3])
        : "r"(a0), "r"(a1), "r"(a2), "r"(a3), "r"(b0), "r"(b1));
}

// ------- fused init: detect dtype + zero counters + split weights + pack x --
__global__ void k_init(const int* __restrict__ ei32, const float* __restrict__ xp,
                       const float* __restrict__ W0, const float* __restrict__ W1,
                       const float* __restrict__ W2, const float* __restrict__ W3,
                       const float* __restrict__ W4){
    int bid = blockIdx.x;
    if (bid == 0){
        __shared__ int anynz;
        if (threadIdx.x == 0) anynz = 0;
        __syncthreads();
        bool nz = false;
        #pragma unroll
        for (int j = 0; j < 8; ++j){
            int i = threadIdx.x*8 + j;
            if (ei32[2*i + 1] != 0) nz = true;
        }
        if (__ballot_sync(0xffffffffu, nz) && (threadIdx.x & 31) == 0)
            atomicExch(&anynz, 1);
        __syncthreads();
        if (threadIdx.x == 0) g_is64 = anynz ? 0 : 1;
    } else if (bid < 1 + ZERO_B){
        int i = (bid - 1)*256 + threadIdx.x;
        if (i < NNODES){ g_cnt[i] = 0; g_fill[i] = 0; }
    } else if (bid < 1 + ZERO_B + WSPL_B){
        int i = (bid - 1 - ZERO_B)*256 + threadIdx.x;
        if (i < WP_TOT){
            const float* src; int p, NC;
            if (i < 32768){
                int r = i >> 13;  p = i & 8191;  NC = 128;
                src = (r == 0) ? W0 : (r == 1) ? W1 : (r == 2) ? W2 : W3;
            } else { src = W4; p = i - 32768; NC = 64; }
            int kp = p / NC, n = p % NC, k = 2*kp;
            float w0 = src[k*NC + n];
            float w1 = src[(k+1)*NC + n];
            g_wh2[i] = packh2(w0, w1);
            g_wl2[i] = packsplit_lo(w0, w1);
        }
    } else {
        // pack x into half2 rows: 1.6M float4 -> 3.2M u32, 2 float4/thread
        int t = (bid - 1 - ZERO_B - WSPL_B)*256 + threadIdx.x;
        const float4* x4 = (const float4*)xp;
        #pragma unroll
        for (int it = 0; it < 2; ++it){
            int u = t + it*(XPK_B*256);
            if (u < NNODES*32){
                float4 v = x4[u];
                g_xh[2*u]   = packh2(v.x, v.y);
                g_xh[2*u+1] = packh2(v.z, v.w);
            }
        }
    }
}

// ---------------- CSR build (4 edges/thread, vectorized) --------------------
__device__ __forceinline__ void load4_dst(const void* ei, int e4, int* d){
    if (g_is64){
        const long long* p = (const long long*)ei + NEDGES + e4;
        longlong2 v0 = *(const longlong2*)p;
        longlong2 v1 = *(const longlong2*)(p + 2);
        d[0] = clampN((int)v0.x); d[1] = clampN((int)v0.y);
        d[2] = clampN((int)v1.x); d[3] = clampN((int)v1.y);
    } else {
        int4 v = *(const int4*)((const int*)ei + NEDGES + e4);
        d[0] = clampN(v.x); d[1] = clampN(v.y); d[2] = clampN(v.z); d[3] = clampN(v.w);
    }
}
__device__ __forceinline__ void load4_src(const void* ei, int e4, int* s){
    if (g_is64){
        const long long* p = (const long long*)ei + e4;
        longlong2 v0 = *(const longlong2*)p;
        longlong2 v1 = *(const longlong2*)(p + 2);
        s[0] = clampN((int)v0.x); s[1] = clampN((int)v0.y);
        s[2] = clampN((int)v1.x); s[3] = clampN((int)v1.y);
    } else {
        int4 v = *(const int4*)((const int*)ei + e4);
        s[0] = clampN(v.x); s[1] = clampN(v.y); s[2] = clampN(v.z); s[3] = clampN(v.w);
    }
}

__global__ void k_hist(const void* __restrict__ ei){
    int e4 = (blockIdx.x*blockDim.x + threadIdx.x) * 4;
    if (e4 >= NEDGES) return;
    int d[4]; load4_dst(ei, e4, d);
    #pragma unroll
    for (int j = 0; j < 4; ++j) atomicAdd(&g_cnt[d[j]], 1);
}

__global__ void k_scan1(){
    __shared__ int s[512];
    int i = blockIdx.x*512 + threadIdx.x;
    s[threadIdx.x] = (i < NNODES) ? g_cnt[i] : 0;
    __syncthreads();
    for (int st = 256; st > 0; st >>= 1){
        if (threadIdx.x < st) s[threadIdx.x] += s[threadIdx.x + st];
        __syncthreads();
    }
    if (threadIdx.x == 0) g_bsums[blockIdx.x] = s[0];
}

__global__ void k_scan3(){
    __shared__ int s[512];
    __shared__ int base;
    int i = blockIdx.x*512 + threadIdx.x;
    int v = (i < NNODES) ? g_cnt[i] : 0;
    s[threadIdx.x] = v;
    if (threadIdx.x == 0){
        int acc = 0;
        for (int j = 0; j < blockIdx.x; ++j) acc += g_bsums[j];
        base = acc;
    }
    __syncthreads();
    for (int st = 1; st < 512; st <<= 1){
        int t = 0;
        if (threadIdx.x >= st) t = s[threadIdx.x - st];
        __syncthreads();
        s[threadIdx.x] += t;
        __syncthreads();
    }
    if (i < NNODES) g_rowptr[i] = base + s[threadIdx.x] - v;
    if (i == NNODES-1) g_rowptr[NNODES] = NEDGES;
}

__global__ void k_scatter(const void* __restrict__ ei){
    int e4 = (blockIdx.x*blockDim.x + threadIdx.x) * 4;
    if (e4 >= NEDGES) return;
    int d[4], s[4];
    load4_dst(ei, e4, d);
    load4_src(ei, e4, s);
    #pragma unroll
    for (int j = 0; j < 4; ++j){
        int p = atomicAdd(&g_fill[d[j]], 1);
        int idx = g_rowptr[d[j]] + p;
        if (idx >= 0 && idx < NEDGES) g_srcs[idx] = s[j];
    }
}

// --------- GIN aggregation from PACKED HALF rows, fp32 accumulate ----------
// g_z[i] = (1+eps)*H[i] + sum_{j in N(i)} H[j]
// Warp per node; 4 edges per iteration via 4 independent loads into 4
// independent accumulator chains (MLP>=4), scalar tail for remainder.
template<int SRCBUF>   // 0 = g_xh, 1 = g_hh
__global__ void k_agg(const float* __restrict__ epsp){
    int gw   = (blockIdx.x*blockDim.x + threadIdx.x) >> 5;
    int lane = threadIdx.x & 31;
    if (gw >= NNODES) return;
    const uint2* H = (const uint2*)(SRCBUF == 0 ? g_xh : g_hh);  // 32 uint2/row
    float scale = 1.0f + *epsp;
    uint2 sv = H[(size_t)gw*32 + lane];
    float2 s0 = h2f2(sv.x), s1 = h2f2(sv.y);
    float4 a0, a1, a2, a3;
    a0.x = s0.x*scale; a0.y = s0.y*scale; a0.z = s1.x*scale; a0.w = s1.y*scale;
    a1 = make_float4(0.f,0.f,0.f,0.f);
    a2 = make_float4(0.f,0.f,0.f,0.f);
    a3 = make_float4(0.f,0.f,0.f,0.f);

    int p  = g_rowptr[gw];
    int pe = g_rowptr[gw + 1];

    for (; p + 4 <= pe; p += 4){
        int i0 = __ldg(&g_srcs[p]);
        int i1 = __ldg(&g_srcs[p+1]);
        int i2 = __ldg(&g_srcs[p+2]);
        int i3 = __ldg(&g_srcs[p+3]);
        uint2 v0 = H[(size_t)i0*32 + lane];
        uint2 v1 = H[(size_t)i1*32 + lane];
        uint2 v2 = H[(size_t)i2*32 + lane];
        uint2 v3 = H[(size_t)i3*32 + lane];
        float2 p0 = h2f2(v0.x), q0 = h2f2(v0.y);
        float2 p1 = h2f2(v1.x), q1 = h2f2(v1.y);
        float2 p2 = h2f2(v2.x), q2 = h2f2(v2.y);
        float2 p3 = h2f2(v3.x), q3 = h2f2(v3.y);
        a0.x += p0.x; a0.y += p0.y; a0.z += q0.x; a0.w += q0.y;
        a1.x += p1.x; a1.y += p1.y; a1.z += q1.x; a1.w += q1.y;
        a2.x += p2.x; a2.y += p2.y; a2.z += q2.x; a2.w += q2.y;
        a3.x += p3.x; a3.y += p3.y; a3.z += q3.x; a3.w += q3.y;
    }
    for (; p < pe; ++p){
        int i0 = __ldg(&g_srcs[p]);
        uint2 v0 = H[(size_t)i0*32 + lane];
        float2 p0 = h2f2(v0.x), q0 = h2f2(v0.y);
        a1.x += p0.x; a1.y += p0.y; a1.z += q0.x; a1.w += q0.y;
    }
    a0.x += a1.x + a2.x + a3.x;
    a0.y += a1.y + a2.y + a3.y;
    a0.z += a1.z + a2.z + a3.z;
    a0.w += a1.w + a2.w + a3.w;
    ((float4*)g_z)[(size_t)gw*32 + lane] = a0;
}

// ---------------- tensor-core GEMM (split-FP16, 3 MMAs, m16n8k16) ----------
// HOUT=false: dst = fp32 buf<DST>.  HOUT=true: dst = packed half2 g_hh.
template<int SRC, int DST, bool HOUT>
__global__ void __launch_bounds__(256)
k_mma(int woff, const float* __restrict__ bias){
    constexpr int NC = 128;
    constexpr int NT = 8;
    __shared__ __align__(16) uint32_t Ah2[16][136];
    __shared__ __align__(16) uint32_t Al2[16][136];
    __shared__ __align__(16) uint32_t Wh2s[16][136];
    __shared__ __align__(16) uint32_t Wl2s[16][136];

    const int tid  = threadIdx.x;
    const int wid  = tid >> 5;
    const int lane = tid & 31;
    const int qr   = lane >> 2;
    const int qc   = lane & 3;
    const int wm   = (wid & 3) * 32;
    const int wn   = (wid >> 2) * 64;

    float acc[2][NT][4];
    #pragma unroll
    for (int nt = 0; nt < NT; ++nt){
        float b0 = bias[wn + nt*8 + qc*2];
        float b1 = bias[wn + nt*8 + qc*2 + 1];
        #pragma unroll
        for (int mt = 0; mt < 2; ++mt){
            acc[mt][nt][0] = b0; acc[mt][nt][1] = b1;
            acc[mt][nt][2] = b0; acc[mt][nt][3] = b1;
        }
    }

    const float* Ablk = buf<SRC>() + (size_t)blockIdx.x * 128 * 128;

    for (int kc = 0; kc < 4; ++kc){
        #pragma unroll
        for (int j = 0; j < 4; ++j){
            int idx = tid + j*256;
            int row = idx >> 3;
            int c4  = idx & 7;
            float4 v = *(const float4*)(Ablk + row*128 + kc*32 + c4*4);
            Ah2[2*c4    ][row] = packh2(v.x, v.y);
            Ah2[2*c4 + 1][row] = packh2(v.z, v.w);
            Al2[2*c4    ][row] = packsplit_lo(v.x, v.y);
            Al2[2*c4 + 1][row] = packsplit_lo(v.z, v.w);
        }
        #pragma unroll
        for (int j = 0; j < 2; ++j){
            int u  = tid + j*256;
            int kp = u >> 5;
            int n4 = (u & 31) * 4;
            int g  = woff + (kc*16 + kp)*NC + n4;
            *(uint4*)&Wh2s[kp][n4] = *(const uint4*)(g_wh2 + g);
            *(uint4*)&Wl2s[kp][n4] = *(const uint4*)(g_wl2 + g);
        }
        __syncthreads();

        #pragma unroll
        for (int ksub = 0; ksub < 2; ++ksub){
            const int kb = ksub*8;
            uint32_t ah[2][4], al[2][4];
            #pragma unroll
            for (int mt = 0; mt < 2; ++mt){
                int m0 = wm + mt*16 + qr;
                ah[mt][0] = Ah2[kb+qc  ][m0];   ah[mt][1] = Ah2[kb+qc  ][m0+8];
                ah[mt][2] = Ah2[kb+qc+4][m0];   ah[mt][3] = Ah2[kb+qc+4][m0+8];
                al[mt][0] = Al2[kb+qc  ][m0];   al[mt][1] = Al2[kb+qc  ][m0+8];
                al[mt][2] = Al2[kb+qc+4][m0];   al[mt][3] = Al2[kb+qc+4][m0+8];
            }
            #pragma unroll
            for (int nt = 0; nt < NT; ++nt){
                int n0 = wn + nt*8 + qr;
                uint32_t bh0 = Wh2s[kb+qc][n0], bh1 = Wh2s[kb+qc+4][n0];
                uint32_t bl0 = Wl2s[kb+qc][n0], bl1 = Wl2s[kb+qc+4][n0];
                #pragma unroll
                for (int mt = 0; mt < 2; ++mt){
                    mma16(acc[mt][nt], ah[mt][0],ah[mt][1],ah[mt][2],ah[mt][3], bh0,bh1);
                    mma16(acc[mt][nt], ah[mt][0],ah[mt][1],ah[mt][2],ah[mt][3], bl0,bl1);
                    mma16(acc[mt][nt], al[mt][0],al[mt][1],al[mt][2],al[mt][3], bh0,bh1);
                }
            }
        }
        __syncthreads();
    }

    if (HOUT){
        uint32_t* Og = g_hh + (size_t)blockIdx.x * 128 * 64;
        #pragma unroll
        for (int mt = 0; mt < 2; ++mt){
            #pragma unroll
            for (int nt = 0; nt < NT; ++nt){
                int row = wm + mt*16 + qr;
                int c2  = (wn >> 1) + nt*4 + qc;
                Og[(row    )*64 + c2] = packh2(fmaxf(acc[mt][nt][0],0.f), fmaxf(acc[mt][nt][1],0.f));
                Og[(row + 8)*64 + c2] = packh2(fmaxf(acc[mt][nt][2],0.f), fmaxf(acc[mt][nt][3],0.f));
            }
        }
    } else {
        float* Og = buf<DST>() + (size_t)blockIdx.x * 128 * NC;
        #pragma unroll
        for (int mt = 0; mt < 2; ++mt){
            #pragma unroll
            for (int nt = 0; nt < NT; ++nt){
                int row = wm + mt*16 + qr;
                int col = wn + nt*8 + qc*2;
                float2 v0 = make_float2(fmaxf(acc[mt][nt][0],0.f), fmaxf(acc[mt][nt][1],0.f));
                float2 v1 = make_float2(fmaxf(acc[mt][nt][2],0.f), fmaxf(acc[mt][nt][3],0.f));
                *(float2*)(Og + (row    )*NC + col) = v0;
                *(float2*)(Og + (row + 8)*NC + col) = v1;
            }
        }
    }
}

// ---------------- classifier GEMM (NC=64) + fused log_softmax --------------
__global__ void __launch_bounds__(256)
k_mma_lsm(int woff, const float* __restrict__ bias, float* __restrict__ out){
    constexpr int NC = 64;
    constexpr int NT = 4;
    __shared__ __align__(16) uint32_t sm[4*16*136];
    uint32_t (*Ah2 )[136] = (uint32_t(*)[136])(sm);
    uint32_t (*Al2 )[136] = (uint32_t(*)[136])(sm + 16*136);
    uint32_t (*Wh2s)[136] = (uint32_t(*)[136])(sm + 32*136);
    uint32_t (*Wl2s)[136] = (uint32_t(*)[136])(sm + 48*136);

    const int tid  = threadIdx.x;
    const int wid  = tid >> 5;
    const int lane = tid & 31;
    const int qr   = lane >> 2;
    const int qc   = lane & 3;
    const int wm   = (wid & 3) * 32;
    const int wn   = (wid >> 2) * 32;

    float acc[2][NT][4];
    #pragma unroll
    for (int nt = 0; nt < NT; ++nt){
        float b0 = bias[wn + nt*8 + qc*2];
        float b1 = bias[wn + nt*8 + qc*2 + 1];
        #pragma unroll
        for (int mt = 0; mt < 2; ++mt){
            acc[mt][nt][0] = b0; acc[mt][nt][1] = b1;
            acc[mt][nt][2] = b0; acc[mt][nt][3] = b1;
        }
    }

    const float* Ablk = buf<2>() + (size_t)blockIdx.x * 128 * 128;

    for (int kc = 0; kc < 4; ++kc){
        #pragma unroll
        for (int j = 0; j < 4; ++j){
            int idx = tid + j*256;
            int row = idx >> 3;
            int c4  = idx & 7;
            float4 v = *(const float4*)(Ablk + row*128 + kc*32 + c4*4);
            Ah2[2*c4    ][row] = packh2(v.x, v.y);
            Ah2[2*c4 + 1][row] = packh2(v.z, v.w);
            Al2[2*c4    ][row] = packsplit_lo(v.x, v.y);
            Al2[2*c4 + 1][row] = packsplit_lo(v.z, v.w);
        }
        {
            int kp = tid >> 4;
            int n4 = (tid & 15) * 4;
            int g  = woff + (kc*16 + kp)*NC + n4;
            *(uint4*)&Wh2s[kp][n4] = *(const uint4*)(g_wh2 + g);
            *(uint4*)&Wl2s[kp][n4] = *(const uint4*)(g_wl2 + g);
        }
        __syncthreads();

        #pragma unroll
        for (int ksub = 0; ksub < 2; ++ksub){
            const int kb = ksub*8;
            uint32_t ah[2][4], al[2][4];
            #pragma unroll
            for (int mt = 0; mt < 2; ++mt){
                int m0 = wm + mt*16 + qr;
                ah[mt][0] = Ah2[kb+qc  ][m0];   ah[mt][1] = Ah2[kb+qc  ][m0+8];
                ah[mt][2] = Ah2[kb+qc+4][m0];   ah[mt][3] = Ah2[kb+qc+4][m0+8];
                al[mt][0] = Al2[kb+qc  ][m0];   al[mt][1] = Al2[kb+qc  ][m0+8];
                al[mt][2] = Al2[kb+qc+4][m0];   al[mt][3] = Al2[kb+qc+4][m0+8];
            }
            #pragma unroll
            for (int nt = 0; nt < NT; ++nt){
                int n0 = wn + nt*8 + qr;
                uint32_t bh0 = Wh2s[kb+qc][n0], bh1 = Wh2s[kb+qc+4][n0];
                uint32_t bl0 = Wl2s[kb+qc][n0], bl1 = Wl2s[kb+qc+4][n0];
                #pragma unroll
                for (int mt = 0; mt < 2; ++mt){
                    mma16(acc[mt][nt], ah[mt][0],ah[mt][1],ah[mt][2],ah[mt][3], bh0,bh1);
                    mma16(acc[mt][nt], ah[mt][0],ah[mt][1],ah[mt][2],ah[mt][3], bl0,bl1);
                    mma16(acc[mt][nt], al[mt][0],al[mt][1],al[mt][2],al[mt][3], bh0,bh1);
                }
            }
        }
        __syncthreads();
    }

    float (*tile)[65] = (float(*)[65])sm;
    #pragma unroll
    for (int mt = 0; mt < 2; ++mt)
        #pragma unroll
        for (int nt = 0; nt < NT; ++nt){
            int row = wm + mt*16 + qr;
            int col = wn + nt*8 + qc*2;
            tile[row    ][col]   = acc[mt][nt][0];
            tile[row    ][col+1] = acc[mt][nt][1];
            tile[row + 8][col]   = acc[mt][nt][2];
            tile[row + 8][col+1] = acc[mt][nt][3];
        }
    __syncthreads();

    for (int r = 0; r < 16; ++r){
        int row  = wid*16 + r;
        int node = blockIdx.x*128 + row;
        if (node >= NNODES) continue;
        float a = tile[row][lane];
        float b = tile[row][lane + 32];
        float m = fmaxf(a, b);
        #pragma unroll
        for (int o = 16; o > 0; o >>= 1) m = fmaxf(m, __shfl_xor_sync(0xffffffffu, m, o));
        float s = expf(a - m) + expf(b - m);
        #pragma unroll
        for (int o = 16; o > 0; o >>= 1) s += __shfl_xor_sync(0xffffffffu, s, o);
        float ls = m + logf(s);
        out[(size_t)node*OUTC + lane]      = a - ls;
        out[(size_t)node*OUTC + lane + 32] = b - ls;
    }
}

// ---------------- launch: kernel launches ONLY, size-based input mapping ---
extern "C" void kernel_launch(void* const* d_in, const int* in_sizes, int n_in,
                              void* d_out, int out_size){
    const float* x = 0; const void* ei = 0;
    const float* Wl = 0; const float* bl = 0;
    const float* epsv[2] = {0,0};
    const float* Wv[4]   = {0,0,0,0};
    const float* bv[4]   = {0,0,0,0};
    int neps = 0, nW = 0, nb = 0;
    for (int i = 0; i < n_in; ++i){
        long long s = in_sizes[i];
        if      (s == 6400000) x  = (const float*)d_in[i];
        else if (s == 1600000) ei = d_in[i];
        else if (s == 8192)    Wl = (const float*)d_in[i];
        else if (s == 64)      bl = (const float*)d_in[i];
        else if (s == 1   && neps < 2) epsv[neps++] = (const float*)d_in[i];
        else if (s == 16384 && nW < 4) Wv[nW++]     = (const float*)d_in[i];
        else if (s == 128  && nb  < 4) bv[nb++]     = (const float*)d_in[i];
    }
    if (!x || !ei || !Wl || !bl || neps < 2 || nW < 4 || nb < 4) return;
    float* out = (float*)d_out;

    const int EB4 = (NEDGES/4 + 255) / 256;
    const int WB  = (NNODES*32 + 255) / 256;

    k_init   <<<1 + ZERO_B + WSPL_B + XPK_B, 256>>>((const int*)ei, x,
                                                    Wv[0], Wv[1], Wv[2], Wv[3], Wl);
    k_hist   <<<EB4, 256>>>(ei);
    k_scan1  <<<SCAN_B, 512>>>();
    k_scan3  <<<SCAN_B, 512>>>();
    k_scatter<<<EB4, 256>>>(ei);

    // layer 1: z = agg(x_h16); t = relu(z@W11+b11); h1 = relu(t@W12+b12) -> g_hh (half)
    k_agg<0><<<WB, 256>>>(epsv[0]);
    k_mma<0,1,false><<<MTILES, 256>>>(0,    bv[0]);
    k_mma<1,2,true ><<<MTILES, 256>>>(8192, bv[1]);

    // layer 2: z = agg(h1_h16); t = relu(z@W21+b21); h2 = relu(t@W22+b22) -> g_h (fp32)
    k_agg<1><<<WB, 256>>>(epsv[1]);
    k_mma<0,1,false><<<MTILES, 256>>>(16384, bv[2]);
    k_mma<1,2,false><<<MTILES, 256>>>(24576, bv[3]);

    // classifier + fused log_softmax
    k_mma_lsm<<<MTILES, 256>>>(32768, bl, out);
}

// round 17
// speedup vs baseline: 1.0808x; 1.0808x over previous
#include <cuda_runtime.h>
#include <cuda_fp16.h>
#include <cstdint>

#define NNODES 50000
#define NEDGES 800000
#define MTILES 391
#define NPAD   (MTILES*128)   // 50048
#define HDIM   128
#define OUTC   64
#define SCAN_B 98             // ceil(50000/512)
#define ZERO_B 196            // ceil(50000/256)
#define WP_TOT (4*8192 + 4096)   // packed half2 pairs: 4x(64*128) + 64*64
#define WSPL_B 144            // WP_TOT/256
#define XPK_B  3125           // x-pack blocks (1.6M float4 / (256*2))

// ------------- scratch: __device__ globals, touched ONLY from device code --
__device__ __align__(16) float    g_z[(size_t)NPAD*HDIM];
__device__ __align__(16) float    g_h[(size_t)NPAD*HDIM];
__device__ __align__(16) uint32_t g_xh[(size_t)NPAD*64];   // x as packed half2
__device__ __align__(16) uint32_t g_hh[(size_t)NPAD*64];   // h1 as packed half2
__device__ __align__(16) uint32_t g_wh2[WP_TOT];
__device__ __align__(16) uint32_t g_wl2[WP_TOT];
__device__ int g_cnt[NNODES];
__device__ int g_fill[NNODES];
__device__ int g_rowptr[NNODES+1];
__device__ int g_srcs[NEDGES];
__device__ int g_bsums[SCAN_B];
__device__ int g_is64;

__device__ __forceinline__ int clampN(int i){
    i = max(i, 0);
    return min(i, NNODES - 1);
}

__device__ __forceinline__ uint32_t packh2(float a, float b){
    __half2 h = __floats2half2_rn(a, b);
    return *reinterpret_cast<uint32_t*>(&h);
}
__device__ __forceinline__ uint32_t packsplit_lo(float a, float b){
    __half ha = __float2half_rn(a), hb = __float2half_rn(b);
    __half2 l = __halves2half2(__float2half_rn(a - __half2float(ha)),
                               __float2half_rn(b - __half2float(hb)));
    return *reinterpret_cast<uint32_t*>(&l);
}
__device__ __forceinline__ float2 h2f2(uint32_t u){
    return __half22float2(*reinterpret_cast<__half2*>(&u));
}

__device__ __forceinline__ void mma16(float* c, uint32_t a0, uint32_t a1,
                                      uint32_t a2, uint32_t a3,
                                      uint32_t b0, uint32_t b1){
    asm("mma.sync.aligned.m16n8k16.row.col.f32.f16.f16.f32 "
        "{%0,%1,%2,%3},{%4,%5,%6,%7},{%8,%9},{%0,%1,%2,%3};"
        : "+f"(c[0]), "+f"(c[1]), "+f"(c[2]), "+f"(c[3])
        : "r"(a0), "r"(a1), "r"(a2), "r"(a3), "r"(b0), "r"(b1));
}

// ------- fused init: detect dtype + zero counters + split weights + pack x --
__global__ void k_init(const int* __restrict__ ei32, const float* __restrict__ xp,
                       const float* __restrict__ W0, const float* __restrict__ W1,
                       const float* __restrict__ W2, const float* __restrict__ W3,
                       const float* __restrict__ W4){
    int bid = blockIdx.x;
    if (bid == 0){
        __shared__ int anynz;
        if (threadIdx.x == 0) anynz = 0;
        __syncthreads();
        bool nz = false;
        #pragma unroll
        for (int j = 0; j < 8; ++j){
            int i = threadIdx.x*8 + j;
            if (ei32[2*i + 1] != 0) nz = true;
        }
        if (__ballot_sync(0xffffffffu, nz) && (threadIdx.x & 31) == 0)
            atomicExch(&anynz, 1);
        __syncthreads();
        if (threadIdx.x == 0) g_is64 = anynz ? 0 : 1;
    } else if (bid < 1 + ZERO_B){
        int i = (bid - 1)*256 + threadIdx.x;
        if (i < NNODES){ g_cnt[i] = 0; g_fill[i] = 0; }
    } else if (bid < 1 + ZERO_B + WSPL_B){
        int i = (bid - 1 - ZERO_B)*256 + threadIdx.x;
        if (i < WP_TOT){
            const float* src; int p, NC;
            if (i < 32768){
                int r = i >> 13;  p = i & 8191;  NC = 128;
                src = (r == 0) ? W0 : (r == 1) ? W1 : (r == 2) ? W2 : W3;
            } else { src = W4; p = i - 32768; NC = 64; }
            int kp = p / NC, n = p % NC, k = 2*kp;
            float w0 = src[k*NC + n];
            float w1 = src[(k+1)*NC + n];
            g_wh2[i] = packh2(w0, w1);
            g_wl2[i] = packsplit_lo(w0, w1);
        }
    } else {
        int t = (bid - 1 - ZERO_B - WSPL_B)*256 + threadIdx.x;
        const float4* x4 = (const float4*)xp;
        #pragma unroll
        for (int it = 0; it < 2; ++it){
            int u = t + it*(XPK_B*256);
            if (u < NNODES*32){
                float4 v = x4[u];
                g_xh[2*u]   = packh2(v.x, v.y);
                g_xh[2*u+1] = packh2(v.z, v.w);
            }
        }
    }
}

// ---------------- CSR build (4 edges/thread, vectorized) --------------------
__device__ __forceinline__ void load4_dst(const void* ei, int e4, int* d){
    if (g_is64){
        const long long* p = (const long long*)ei + NEDGES + e4;
        longlong2 v0 = *(const longlong2*)p;
        longlong2 v1 = *(const longlong2*)(p + 2);
        d[0] = clampN((int)v0.x); d[1] = clampN((int)v0.y);
        d[2] = clampN((int)v1.x); d[3] = clampN((int)v1.y);
    } else {
        int4 v = *(const int4*)((const int*)ei + NEDGES + e4);
        d[0] = clampN(v.x); d[1] = clampN(v.y); d[2] = clampN(v.z); d[3] = clampN(v.w);
    }
}
__device__ __forceinline__ void load4_src(const void* ei, int e4, int* s){
    if (g_is64){
        const long long* p = (const long long*)ei + e4;
        longlong2 v0 = *(const longlong2*)p;
        longlong2 v1 = *(const longlong2*)(p + 2);
        s[0] = clampN((int)v0.x); s[1] = clampN((int)v0.y);
        s[2] = clampN((int)v1.x); s[3] = clampN((int)v1.y);
    } else {
        int4 v = *(const int4*)((const int*)ei + e4);
        s[0] = clampN(v.x); s[1] = clampN(v.y); s[2] = clampN(v.z); s[3] = clampN(v.w);
    }
}

__global__ void k_hist(const void* __restrict__ ei){
    int e4 = (blockIdx.x*blockDim.x + threadIdx.x) * 4;
    if (e4 >= NEDGES) return;
    int d[4]; load4_dst(ei, e4, d);
    #pragma unroll
    for (int j = 0; j < 4; ++j) atomicAdd(&g_cnt[d[j]], 1);
}

__global__ void k_scan1(){
    __shared__ int s[512];
    int i = blockIdx.x*512 + threadIdx.x;
    s[threadIdx.x] = (i < NNODES) ? g_cnt[i] : 0;
    __syncthreads();
    for (int st = 256; st > 0; st >>= 1){
        if (threadIdx.x < st) s[threadIdx.x] += s[threadIdx.x + st];
        __syncthreads();
    }
    if (threadIdx.x == 0) g_bsums[blockIdx.x] = s[0];
}

__global__ void k_scan3(){
    __shared__ int s[512];
    __shared__ int base;
    int i = blockIdx.x*512 + threadIdx.x;
    int v = (i < NNODES) ? g_cnt[i] : 0;
    s[threadIdx.x] = v;
    if (threadIdx.x == 0){
        int acc = 0;
        for (int j = 0; j < blockIdx.x; ++j) acc += g_bsums[j];
        base = acc;
    }
    __syncthreads();
    for (int st = 1; st < 512; st <<= 1){
        int t = 0;
        if (threadIdx.x >= st) t = s[threadIdx.x - st];
        __syncthreads();
        s[threadIdx.x] += t;
        __syncthreads();
    }
    if (i < NNODES) g_rowptr[i] = base + s[threadIdx.x] - v;
    if (i == NNODES-1) g_rowptr[NNODES] = NEDGES;
}

__global__ void k_scatter(const void* __restrict__ ei){
    int e4 = (blockIdx.x*blockDim.x + threadIdx.x) * 4;
    if (e4 >= NEDGES) return;
    int d[4], s[4];
    load4_dst(ei, e4, d);
    load4_src(ei, e4, s);
    #pragma unroll
    for (int j = 0; j < 4; ++j){
        int p = atomicAdd(&g_fill[d[j]], 1);
        int idx = g_rowptr[d[j]] + p;
        if (idx >= 0 && idx < NEDGES) g_srcs[idx] = s[j];
    }
}

// --------- GIN aggregation from PACKED HALF rows, fp32 accumulate ----------
// (R15-proven form: coalesced index load + shuffle broadcast)
template<int SRCBUF>   // 0 = g_xh, 1 = g_hh
__global__ void k_agg(const float* __restrict__ epsp){
    int gw   = (blockIdx.x*blockDim.x + threadIdx.x) >> 5;
    int lane = threadIdx.x & 31;
    if (gw >= NNODES) return;
    const uint2* H = (const uint2*)(SRCBUF == 0 ? g_xh : g_hh);  // 32 uint2/row
    float scale = 1.0f + *epsp;
    uint2 sv = H[(size_t)gw*32 + lane];
    float2 s0 = h2f2(sv.x), s1 = h2f2(sv.y);
    float4 acc;
    acc.x = s0.x*scale; acc.y = s0.y*scale;
    acc.z = s1.x*scale; acc.w = s1.y*scale;
    int p  = g_rowptr[gw];
    int pe = g_rowptr[gw + 1];
    while (p < pe){
        int cnt = min(pe - p, 32);
        int idx = (lane < cnt) ? g_srcs[p + lane] : 0;
        for (int j = 0; j < cnt; ++j){
            int s = __shfl_sync(0xffffffffu, idx, j);
            uint2 v = H[(size_t)s*32 + lane];
            float2 v0 = h2f2(v.x), v1 = h2f2(v.y);
            acc.x += v0.x; acc.y += v0.y; acc.z += v1.x; acc.w += v1.y;
        }
        p += cnt;
    }
    ((float4*)g_z)[(size_t)gw*32 + lane] = acc;
}

// ------------- fused 2-GEMM MLP (split-FP16, 3 MMAs, m16n8k16) -------------
// h = relu( relu(z@W1+b1) @ W2 + b2 ), K=N=128, per 128-row block.
// GEMM1 result stays in registers; t-slices are spilled (relu+hi/lo split)
// directly into the GEMM2 A-staging smem by the 4 owning warps per K-chunk.
// HOUT=true: write packed half2 to g_hh.  HOUT=false: write fp32 to g_h.
template<bool HOUT>
__global__ void __launch_bounds__(256, 1)
k_mlp(int woff1, const float* __restrict__ bias1,
      int woff2, const float* __restrict__ bias2){
    constexpr int NC = 128;
    constexpr int NT = 8;
    __shared__ __align__(16) uint32_t Ah2[16][136];
    __shared__ __align__(16) uint32_t Al2[16][136];
    __shared__ __align__(16) uint32_t Wh2s[16][136];
    __shared__ __align__(16) uint32_t Wl2s[16][136];

    const int tid  = threadIdx.x;
    const int wid  = tid >> 5;
    const int lane = tid & 31;
    const int qr   = lane >> 2;
    const int qc   = lane & 3;
    const int wm   = (wid & 3) * 32;
    const int wn   = (wid >> 2) * 64;

    // ---- GEMM1: acc1 = z @ W1 + b1 ----
    float acc1[2][NT][4];
    #pragma unroll
    for (int nt = 0; nt < NT; ++nt){
        float b0 = bias1[wn + nt*8 + qc*2];
        float b1 = bias1[wn + nt*8 + qc*2 + 1];
        #pragma unroll
        for (int mt = 0; mt < 2; ++mt){
            acc1[mt][nt][0] = b0; acc1[mt][nt][1] = b1;
            acc1[mt][nt][2] = b0; acc1[mt][nt][3] = b1;
        }
    }
    const float* Ablk = g_z + (size_t)blockIdx.x * 128 * 128;

    for (int kc = 0; kc < 4; ++kc){
        #pragma unroll
        for (int j = 0; j < 4; ++j){
            int idx = tid + j*256;
            int row = idx >> 3;
            int c4  = idx & 7;
            float4 v = *(const float4*)(Ablk + row*128 + kc*32 + c4*4);
            Ah2[2*c4    ][row] = packh2(v.x, v.y);
            Ah2[2*c4 + 1][row] = packh2(v.z, v.w);
            Al2[2*c4    ][row] = packsplit_lo(v.x, v.y);
            Al2[2*c4 + 1][row] = packsplit_lo(v.z, v.w);
        }
        #pragma unroll
        for (int j = 0; j < 2; ++j){
            int u  = tid + j*256;
            int kp = u >> 5;
            int n4 = (u & 31) * 4;
            int g  = woff1 + (kc*16 + kp)*NC + n4;
            *(uint4*)&Wh2s[kp][n4] = *(const uint4*)(g_wh2 + g);
            *(uint4*)&Wl2s[kp][n4] = *(const uint4*)(g_wl2 + g);
        }
        __syncthreads();
        #pragma unroll
        for (int ksub = 0; ksub < 2; ++ksub){
            const int kb = ksub*8;
            uint32_t ah[2][4], al[2][4];
            #pragma unroll
            for (int mt = 0; mt < 2; ++mt){
                int m0 = wm + mt*16 + qr;
                ah[mt][0] = Ah2[kb+qc  ][m0];   ah[mt][1] = Ah2[kb+qc  ][m0+8];
                ah[mt][2] = Ah2[kb+qc+4][m0];   ah[mt][3] = Ah2[kb+qc+4][m0+8];
                al[mt][0] = Al2[kb+qc  ][m0];   al[mt][1] = Al2[kb+qc  ][m0+8];
                al[mt][2] = Al2[kb+qc+4][m0];   al[mt][3] = Al2[kb+qc+4][m0+8];
            }
            #pragma unroll
            for (int nt = 0; nt < NT; ++nt){
                int n0 = wn + nt*8 + qr;
                uint32_t bh0 = Wh2s[kb+qc][n0], bh1 = Wh2s[kb+qc+4][n0];
                uint32_t bl0 = Wl2s[kb+qc][n0], bl1 = Wl2s[kb+qc+4][n0];
                #pragma unroll
                for (int mt = 0; mt < 2; ++mt){
                    mma16(acc1[mt][nt], ah[mt][0],ah[mt][1],ah[mt][2],ah[mt][3], bh0,bh1);
                    mma16(acc1[mt][nt], ah[mt][0],ah[mt][1],ah[mt][2],ah[mt][3], bl0,bl1);
                    mma16(acc1[mt][nt], al[mt][0],al[mt][1],al[mt][2],al[mt][3], bh0,bh1);
                }
            }
        }
        __syncthreads();
    }

    // ---- GEMM2: acc2 = relu(acc1) @ W2 + b2, A spilled from registers ----
    float acc2[2][NT][4];
    #pragma unroll
    for (int nt = 0; nt < NT; ++nt){
        float b0 = bias2[wn + nt*8 + qc*2];
        float b1 = bias2[wn + nt*8 + qc*2 + 1];
        #pragma unroll
        for (int mt = 0; mt < 2; ++mt){
            acc2[mt][nt][0] = b0; acc2[mt][nt][1] = b1;
            acc2[mt][nt][2] = b0; acc2[mt][nt][3] = b1;
        }
    }

    #pragma unroll
    for (int kc2 = 0; kc2 < 4; ++kc2){
        // t-slice (cols kc2*32..+32) -> Ah2/Al2, written by the 4 owning warps
        const int owner_wn = (kc2 >> 1) * 64;
        const int ntb      = (kc2 & 1) * 4;
        if (wn == owner_wn){
            #pragma unroll
            for (int j = 0; j < 4; ++j){
                int nt = ntb + j;
                int kp = j*4 + qc;
                #pragma unroll
                for (int mt = 0; mt < 2; ++mt){
                    int row = wm + mt*16 + qr;
                    float t0 = fmaxf(acc1[mt][nt][0], 0.f);
                    float t1 = fmaxf(acc1[mt][nt][1], 0.f);
                    Ah2[kp][row] = packh2(t0, t1);
                    Al2[kp][row] = packsplit_lo(t0, t1);
                    float t2 = fmaxf(acc1[mt][nt][2], 0.f);
                    float t3 = fmaxf(acc1[mt][nt][3], 0.f);
                    Ah2[kp][row + 8] = packh2(t2, t3);
                    Al2[kp][row + 8] = packsplit_lo(t2, t3);
                }
            }
        }
        #pragma unroll
        for (int j = 0; j < 2; ++j){
            int u  = tid + j*256;
            int kp = u >> 5;
            int n4 = (u & 31) * 4;
            int g  = woff2 + (kc2*16 + kp)*NC + n4;
            *(uint4*)&Wh2s[kp][n4] = *(const uint4*)(g_wh2 + g);
            *(uint4*)&Wl2s[kp][n4] = *(const uint4*)(g_wl2 + g);
        }
        __syncthreads();
        #pragma unroll
        for (int ksub = 0; ksub < 2; ++ksub){
            const int kb = ksub*8;
            uint32_t ah[2][4], al[2][4];
            #pragma unroll
            for (int mt = 0; mt < 2; ++mt){
                int m0 = wm + mt*16 + qr;
                ah[mt][0] = Ah2[kb+qc  ][m0];   ah[mt][1] = Ah2[kb+qc  ][m0+8];
                ah[mt][2] = Ah2[kb+qc+4][m0];   ah[mt][3] = Ah2[kb+qc+4][m0+8];
                al[mt][0] = Al2[kb+qc  ][m0];   al[mt][1] = Al2[kb+qc  ][m0+8];
                al[mt][2] = Al2[kb+qc+4][m0];   al[mt][3] = Al2[kb+qc+4][m0+8];
            }
            #pragma unroll
            for (int nt = 0; nt < NT; ++nt){
                int n0 = wn + nt*8 + qr;
                uint32_t bh0 = Wh2s[kb+qc][n0], bh1 = Wh2s[kb+qc+4][n0];
                uint32_t bl0 = Wl2s[kb+qc][n0], bl1 = Wl2s[kb+qc+4][n0];
                #pragma unroll
                for (int mt = 0; mt < 2; ++mt){
                    mma16(acc2[mt][nt], ah[mt][0],ah[mt][1],ah[mt][2],ah[mt][3], bh0,bh1);
                    mma16(acc2[mt][nt], ah[mt][0],ah[mt][1],ah[mt][2],ah[mt][3], bl0,bl1);
                    mma16(acc2[mt][nt], al[mt][0],al[mt][1],al[mt][2],al[mt][3], bh0,bh1);
                }
            }
        }
        __syncthreads();
    }

    if (HOUT){
        uint32_t* Og = g_hh + (size_t)blockIdx.x * 128 * 64;
        #pragma unroll
        for (int mt = 0; mt < 2; ++mt){
            #pragma unroll
            for (int nt = 0; nt < NT; ++nt){
                int row = wm + mt*16 + qr;
                int c2  = (wn >> 1) + nt*4 + qc;
                Og[(row    )*64 + c2] = packh2(fmaxf(acc2[mt][nt][0],0.f), fmaxf(acc2[mt][nt][1],0.f));
                Og[(row + 8)*64 + c2] = packh2(fmaxf(acc2[mt][nt][2],0.f), fmaxf(acc2[mt][nt][3],0.f));
            }
        }
    } else {
        float* Og = g_h + (size_t)blockIdx.x * 128 * NC;
        #pragma unroll
        for (int mt = 0; mt < 2; ++mt){
            #pragma unroll
            for (int nt = 0; nt < NT; ++nt){
                int row = wm + mt*16 + qr;
                int col = wn + nt*8 + qc*2;
                float2 v0 = make_float2(fmaxf(acc2[mt][nt][0],0.f), fmaxf(acc2[mt][nt][1],0.f));
                float2 v1 = make_float2(fmaxf(acc2[mt][nt][2],0.f), fmaxf(acc2[mt][nt][3],0.f));
                *(float2*)(Og + (row    )*NC + col) = v0;
                *(float2*)(Og + (row + 8)*NC + col) = v1;
            }
        }
    }
}

// ---------------- classifier GEMM (NC=64) + fused log_softmax --------------
__global__ void __launch_bounds__(256)
k_mma_lsm(int woff, const float* __restrict__ bias, float* __restrict__ out){
    constexpr int NC = 64;
    constexpr int NT = 4;
    __shared__ __align__(16) uint32_t sm[4*16*136];
    uint32_t (*Ah2 )[136] = (uint32_t(*)[136])(sm);
    uint32_t (*Al2 )[136] = (uint32_t(*)[136])(sm + 16*136);
    uint32_t (*Wh2s)[136] = (uint32_t(*)[136])(sm + 32*136);
    uint32_t (*Wl2s)[136] = (uint32_t(*)[136])(sm + 48*136);

    const int tid  = threadIdx.x;
    const int wid  = tid >> 5;
    const int lane = tid & 31;
    const int qr   = lane >> 2;
    const int qc   = lane & 3;
    const int wm   = (wid & 3) * 32;
    const int wn   = (wid >> 2) * 32;

    float acc[2][NT][4];
    #pragma unroll
    for (int nt = 0; nt < NT; ++nt){
        float b0 = bias[wn + nt*8 + qc*2];
        float b1 = bias[wn + nt*8 + qc*2 + 1];
        #pragma unroll
        for (int mt = 0; mt < 2; ++mt){
            acc[mt][nt][0] = b0; acc[mt][nt][1] = b1;
            acc[mt][nt][2] = b0; acc[mt][nt][3] = b1;
        }
    }

    const float* Ablk = g_h + (size_t)blockIdx.x * 128 * 128;

    for (int kc = 0; kc < 4; ++kc){
        #pragma unroll
        for (int j = 0; j < 4; ++j){
            int idx = tid + j*256;
            int row = idx >> 3;
            int c4  = idx & 7;
            float4 v = *(const float4*)(Ablk + row*128 + kc*32 + c4*4);
            Ah2[2*c4    ][row] = packh2(v.x, v.y);
            Ah2[2*c4 + 1][row] = packh2(v.z, v.w);
            Al2[2*c4    ][row] = packsplit_lo(v.x, v.y);
            Al2[2*c4 + 1][row] = packsplit_lo(v.z, v.w);
        }
        {
            int kp = tid >> 4;
            int n4 = (tid & 15) * 4;
            int g  = woff + (kc*16 + kp)*NC + n4;
            *(uint4*)&Wh2s[kp][n4] = *(const uint4*)(g_wh2 + g);
            *(uint4*)&Wl2s[kp][n4] = *(const uint4*)(g_wl2 + g);
        }
        __syncthreads();

        #pragma unroll
        for (int ksub = 0; ksub < 2; ++ksub){
            const int kb = ksub*8;
            uint32_t ah[2][4], al[2][4];
            #pragma unroll
            for (int mt = 0; mt < 2; ++mt){
                int m0 = wm + mt*16 + qr;
                ah[mt][0] = Ah2[kb+qc  ][m0];   ah[mt][1] = Ah2[kb+qc  ][m0+8];
                ah[mt][2] = Ah2[kb+qc+4][m0];   ah[mt][3] = Ah2[kb+qc+4][m0+8];
                al[mt][0] = Al2[kb+qc  ][m0];   al[mt][1] = Al2[kb+qc  ][m0+8];
                al[mt][2] = Al2[kb+qc+4][m0];   al[mt][3] = Al2[kb+qc+4][m0+8];
            }
            #pragma unroll
            for (int nt = 0; nt < NT; ++nt){
                int n0 = wn + nt*8 + qr;
                uint32_t bh0 = Wh2s[kb+qc][n0], bh1 = Wh2s[kb+qc+4][n0];
                uint32_t bl0 = Wl2s[kb+qc][n0], bl1 = Wl2s[kb+qc+4][n0];
                #pragma unroll
                for (int mt = 0; mt < 2; ++mt){
                    mma16(acc[mt][nt], ah[mt][0],ah[mt][1],ah[mt][2],ah[mt][3], bh0,bh1);
                    mma16(acc[mt][nt], ah[mt][0],ah[mt][1],ah[mt][2],ah[mt][3], bl0,bl1);
                    mma16(acc[mt][nt], al[mt][0],al[mt][1],al[mt][2],al[mt][3], bh0,bh1);
                }
            }
        }
        __syncthreads();
    }

    float (*tile)[65] = (float(*)[65])sm;
    #pragma unroll
    for (int mt = 0; mt < 2; ++mt)
        #pragma unroll
        for (int nt = 0; nt < NT; ++nt){
            int row = wm + mt*16 + qr;
            int col = wn + nt*8 + qc*2;
            tile[row    ][col]   = acc[mt][nt][0];
            tile[row    ][col+1] = acc[mt][nt][1];
            tile[row + 8][col]   = acc[mt][nt][2];
            tile[row + 8][col+1] = acc[mt][nt][3];
        }
    __syncthreads();

    for (int r = 0; r < 16; ++r){
        int row  = wid*16 + r;
        int node = blockIdx.x*128 + row;
        if (node >= NNODES) continue;
        float a = tile[row][lane];
        float b = tile[row][lane + 32];
        float m = fmaxf(a, b);
        #pragma unroll
        for (int o = 16; o > 0; o >>= 1) m = fmaxf(m, __shfl_xor_sync(0xffffffffu, m, o));
        float s = expf(a - m) + expf(b - m);
        #pragma unroll
        for (int o = 16; o > 0; o >>= 1) s += __shfl_xor_sync(0xffffffffu, s, o);
        float ls = m + logf(s);
        out[(size_t)node*OUTC + lane]      = a - ls;
        out[(size_t)node*OUTC + lane + 32] = b - ls;
    }
}

// ---------------- launch: kernel launches ONLY, size-based input mapping ---
extern "C" void kernel_launch(void* const* d_in, const int* in_sizes, int n_in,
                              void* d_out, int out_size){
    const float* x = 0; const void* ei = 0;
    const float* Wl = 0; const float* bl = 0;
    const float* epsv[2] = {0,0};
    const float* Wv[4]   = {0,0,0,0};
    const float* bv[4]   = {0,0,0,0};
    int neps = 0, nW = 0, nb = 0;
    for (int i = 0; i < n_in; ++i){
        long long s = in_sizes[i];
        if      (s == 6400000) x  = (const float*)d_in[i];
        else if (s == 1600000) ei = d_in[i];
        else if (s == 8192)    Wl = (const float*)d_in[i];
        else if (s == 64)      bl = (const float*)d_in[i];
        else if (s == 1   && neps < 2) epsv[neps++] = (const float*)d_in[i];
        else if (s == 16384 && nW < 4) Wv[nW++]     = (const float*)d_in[i];
        else if (s == 128  && nb  < 4) bv[nb++]     = (const float*)d_in[i];
    }
    if (!x || !ei || !Wl || !bl || neps < 2 || nW < 4 || nb < 4) return;
    float* out = (float*)d_out;

    const int EB4 = (NEDGES/4 + 255) / 256;
    const int WB  = (NNODES*32 + 255) / 256;

    k_init   <<<1 + ZERO_B + WSPL_B + XPK_B, 256>>>((const int*)ei, x,
                                                    Wv[0], Wv[1], Wv[2], Wv[3], Wl);
    k_hist   <<<EB4, 256>>>(ei);
    k_scan1  <<<SCAN_B, 512>>>();
    k_scan3  <<<SCAN_B, 512>>>();
    k_scatter<<<EB4, 256>>>(ei);

    // layer 1: z = agg(x_h16); h1 = MLP1(z) -> g_hh (packed half)
    k_agg<0><<<WB, 256>>>(epsv[0]);
    k_mlp<true ><<<MTILES, 256>>>(0, bv[0], 8192, bv[1]);

    // layer 2: z = agg(h1_h16); h2 = MLP2(z) -> g_h (fp32)
    k_agg<1><<<WB, 256>>>(epsv[1]);
    k_mlp<false><<<MTILES, 256>>>(16384, bv[2], 24576, bv[3]);

    // classifier + fused log_softmax
    k_mma_lsm<<<MTILES, 256>>>(32768, bl, out);
}